// round 2
// baseline (speedup 1.0000x reference)
#include <cuda_runtime.h>
#include <math.h>
#include <float.h>
#include <stdint.h>

// Problem constants
#define Bn 32
#define Mn 384
#define Nn 128
#define Cn 92
#define CPL 12          // columns per lane (384/32)

static __device__ __constant__ float kCOST_IOU = 2.0f;
static __device__ __constant__ float kCOST_L1  = 5.0f;
static __device__ __constant__ float kCOST_CAT = 1.0f;
static __device__ __constant__ float kEPS      = 1e-7f;

// Scratch (device globals: allocation-free)
__device__ float  g_cost[(size_t)Bn * Nn * Mn];   // [b][n][m]
__device__ float2 g_stats[Bn * Mn];               // (max, sumexp) per (b,m)
__device__ float4 g_pxy[Bn * Mn];                 // pred xyxy
__device__ float4 g_txy[Bn * Nn];                 // targ xyxy
__device__ int    g_assign[Bn * Nn];
__device__ float  g_loss[Bn];

// ---------------------------------------------------------------------------
// Kernel 1: per-(b,m) softmax stats + pred xyxy; per-(b,n) targ xyxy
// ---------------------------------------------------------------------------
__global__ void prep_kernel(const float* __restrict__ pred_cat,
                            const float* __restrict__ pred_bbox,
                            const float* __restrict__ targ_bbox) {
    int t = blockIdx.x * blockDim.x + threadIdx.x;
    if (t < Bn * Mn) {
        const float* row = pred_cat + (size_t)t * Cn;
        float mx = -FLT_MAX;
        for (int c = 0; c < Cn; c++) mx = fmaxf(mx, row[c]);
        float s = 0.0f;
        for (int c = 0; c < Cn; c++) s += expf(row[c] - mx);
        g_stats[t] = make_float2(mx, s);
        float cx = pred_bbox[t * 4 + 0], cy = pred_bbox[t * 4 + 1];
        float w  = pred_bbox[t * 4 + 2], h  = pred_bbox[t * 4 + 3];
        g_pxy[t] = make_float4(cx - 0.5f * w, cy - 0.5f * h,
                               cx + 0.5f * w, cy + 0.5f * h);
    } else if (t < Bn * Mn + Bn * Nn) {
        int u = t - Bn * Mn;
        float cx = targ_bbox[u * 4 + 0], cy = targ_bbox[u * 4 + 1];
        float w  = targ_bbox[u * 4 + 2], h  = targ_bbox[u * 4 + 3];
        g_txy[u] = make_float4(cx - 0.5f * w, cy - 0.5f * h,
                               cx + 0.5f * w, cy + 0.5f * h);
    }
}

// GIoU-loss + L1 helper (matches reference formula order)
__device__ __forceinline__ float bbox_pair_cost(float4 p, float4 t) {
    float ix1 = fmaxf(p.x, t.x), iy1 = fmaxf(p.y, t.y);
    float ix2 = fminf(p.z, t.z), iy2 = fminf(p.w, t.w);
    float inter = fmaxf(ix2 - ix1, 0.0f) * fmaxf(iy2 - iy1, 0.0f);
    float ap = (p.z - p.x) * (p.w - p.y);
    float at = (t.z - t.x) * (t.w - t.y);
    float un = ap + at - inter;
    float iou = inter / (un + kEPS);
    float cx1 = fminf(p.x, t.x), cy1 = fminf(p.y, t.y);
    float cx2 = fmaxf(p.z, t.z), cy2 = fmaxf(p.w, t.w);
    float ac = (cx2 - cx1) * (cy2 - cy1);
    float giou = iou - (ac - un) / (ac + kEPS);
    float gl = 1.0f - giou;
    float l1 = (fabsf(p.x - t.x) + fabsf(p.y - t.y) +
                fabsf(p.z - t.z) + fabsf(p.w - t.w)) * 0.25f;
    return kCOST_IOU * gl + kCOST_L1 * l1;
}

// ---------------------------------------------------------------------------
// Kernel 2: cost matrix, one block per (b,n), thread per m (coalesced writes)
// ---------------------------------------------------------------------------
__global__ __launch_bounds__(Mn) void cost_kernel(const float* __restrict__ pred_cat,
                                                  const int* __restrict__ targ_cat) {
    int b = blockIdx.y, n = blockIdx.x, m = threadIdx.x;
    int tc = targ_cat[b * Nn + n];
    float4 t4 = g_txy[b * Nn + n];
    float maskf = (tc != 0) ? 1.0f : 0.0f;

    float2 st = g_stats[b * Mn + m];
    float logit = pred_cat[((size_t)(b * Mn + m)) * Cn + tc];
    float prob = expf(logit - st.x) / st.y;
    float cat = kCOST_CAT * (1.0f - prob);

    float bb = bbox_pair_cost(g_pxy[b * Mn + m], t4);
    g_cost[((size_t)(b * Nn + n)) * Mn + m] = cat + bb * maskf;
}

// ---------------------------------------------------------------------------
// Kernel 3: Hungarian (JV) — warp-per-batch solver + fused loss epilogue.
// Block of 384 threads per batch: all threads stage cost & compute loss;
// warp 0 alone runs the solver (no block barriers in the hot loop).
// ---------------------------------------------------------------------------
#define CS_BYTES   (Nn * Mn * 4)             // 196608
#define OFF_U      (CS_BYTES)                // double[Nn+1]
#define OFF_P      (OFF_U + (Nn + 1) * 8)    // int[Mn+1]
#define OFF_WAY    (OFF_P + (Mn + 1) * 4)    // int[Mn+1]
#define SMEM_TOTAL (OFF_WAY + (Mn + 1) * 4)  // ~200 KB

__device__ __forceinline__ unsigned fkey(float f) {
    unsigned b = __float_as_uint(f);
    return (b & 0x80000000u) ? ~b : (b | 0x80000000u);
}

__global__ __launch_bounds__(Mn, 1) void hungarian_kernel(
        const float* __restrict__ pred_cat,
        const int* __restrict__ targ_cat) {
    const unsigned FULL = 0xffffffffu;
    int b = blockIdx.x;
    extern __shared__ unsigned char smem[];
    float*  cs   = (float*)smem;
    double* u_sh = (double*)(smem + OFF_U);
    int*    p_sh = (int*)(smem + OFF_P);
    int*    way  = (int*)(smem + OFF_WAY);

    __shared__ int   a_sh[Nn];
    __shared__ float r1[4], r2[4], r3[4];

    int tid = threadIdx.x;
    int wid = tid >> 5, lane = tid & 31;
    const double DINF = (double)INFINITY;

    // ---- stage cost tile into smem (float4, all 384 threads) ----
    {
        const float4* gc = (const float4*)(g_cost + (size_t)b * Nn * Mn);
        float4* c4 = (float4*)cs;
        #pragma unroll 4
        for (int idx = tid; idx < Nn * Mn / 4; idx += Mn) c4[idx] = gc[idx];
    }
    for (int j = tid; j <= Mn; j += Mn) p_sh[j] = 0;
    if (tid <= Nn) u_sh[tid] = 0.0;
    __syncthreads();

    // ---- solver: warp 0 only ----
    if (wid == 0) {
        double v_reg[CPL], minv_reg[CPL];
        #pragma unroll
        for (int c = 0; c < CPL; c++) v_reg[c] = 0.0;

        for (int i = 1; i <= Nn; i++) {
            unsigned used_mask = 0;
            #pragma unroll
            for (int c = 0; c < CPL; c++) minv_reg[c] = DINF;
            if (lane == 0) p_sh[0] = i;
            __syncwarp();

            int j0 = 0;
            while (true) {
                int i0;
                if (j0 == 0) {
                    i0 = i;
                } else {
                    // owner lane marks j0 used (strided ownership: m = c*32+lane)
                    if (lane == ((j0 - 1) & 31))
                        used_mask |= 1u << ((j0 - 1) >> 5);
                    i0 = p_sh[j0];
                }
                double ui0 = u_sh[i0];
                const float* row = cs + (i0 - 1) * Mn;

                double mv = DINF; int mi = 0x7fffffff;
                #pragma unroll
                for (int c = 0; c < CPL; c++) {
                    if (!(used_mask & (1u << c))) {
                        int m = c * 32 + lane;
                        double cur = ((double)row[m] - ui0) - v_reg[c];
                        if (cur < minv_reg[c]) { minv_reg[c] = cur; way[m + 1] = j0; }
                        if (minv_reg[c] < mv) { mv = minv_reg[c]; mi = m + 1; }
                    }
                }

                // fast path: f32-key REDUX.MIN; exact f64 fallback on f32 ties
                double delta; int k;
                unsigned bits = fkey(__double2float_rn(mv));
                unsigned rmin = __reduce_min_sync(FULL, bits);
                unsigned bal  = __ballot_sync(FULL, bits == rmin);
                if (__popc(bal) == 1) {
                    int w = __ffs(bal) - 1;
                    delta = __shfl_sync(FULL, mv, w);
                    k     = __shfl_sync(FULL, mi, w);
                } else {
                    double rv = mv; int ri = mi;
                    #pragma unroll
                    for (int off = 16; off; off >>= 1) {
                        double ov = __shfl_down_sync(FULL, rv, off);
                        int    oi = __shfl_down_sync(FULL, ri, off);
                        if (ov < rv || (ov == rv && oi < ri)) { rv = ov; ri = oi; }
                    }
                    delta = __shfl_sync(FULL, rv, 0);
                    k     = __shfl_sync(FULL, ri, 0);
                }

                // dual updates (exact numpy float64 op order)
                #pragma unroll
                for (int c = 0; c < CPL; c++) {
                    if (used_mask & (1u << c)) {
                        v_reg[c] -= delta;
                        int pj = p_sh[c * 32 + lane + 1];
                        u_sh[pj] += delta;      // distinct rows across lanes
                    } else {
                        minv_reg[c] -= delta;
                    }
                }
                if (lane == 0) u_sh[i] += delta;  // virtual column 0 (p[0]=i)

                int pk = p_sh[k];
                j0 = k;
                if (pk == 0) break;
            }

            // augment along alternating path
            if (lane == 0) {
                int jj = j0;
                while (jj) { int j1 = way[jj]; p_sh[jj] = p_sh[j1]; jj = j1; }
            }
            __syncwarp();
        }
    }
    __syncthreads();

    // ---- write assignment + build inverse map ----
    {
        int j = tid + 1;
        int pi = p_sh[j];
        if (pi > 0) {
            g_assign[b * Nn + (pi - 1)] = j - 1;
            a_sh[pi - 1] = j - 1;
        }
    }
    __syncthreads();

    // ---- fused per-batch loss ----
    float s_ce = 0.0f, s_bl = 0.0f, s_mk = 0.0f;
    if (tid < Nn) {
        int n  = tid;
        int a  = a_sh[n];
        int tc = targ_cat[b * Nn + n];
        float2 st = g_stats[b * Mn + a];
        float logit = pred_cat[((size_t)(b * Mn + a)) * Cn + tc];
        s_ce = -(logit - st.x - logf(st.y));
        float bl = bbox_pair_cost(g_pxy[b * Mn + a], g_txy[b * Nn + n]);
        s_mk = (tc != 0) ? 1.0f : 0.0f;
        s_bl = bl * s_mk;
    }
    #pragma unroll
    for (int off = 16; off; off >>= 1) {
        s_ce += __shfl_down_sync(FULL, s_ce, off);
        s_bl += __shfl_down_sync(FULL, s_bl, off);
        s_mk += __shfl_down_sync(FULL, s_mk, off);
    }
    if (wid < 4 && lane == 0) { r1[wid] = s_ce; r2[wid] = s_bl; r3[wid] = s_mk; }
    __syncthreads();
    if (tid == 0) {
        float ce_sum = r1[0] + r1[1] + r1[2] + r1[3];
        float bl_sum = r2[0] + r2[1] + r2[2] + r2[3];
        float mk_sum = r3[0] + r3[1] + r3[2] + r3[3];
        g_loss[b] = (ce_sum / (float)Nn) + bl_sum / (mk_sum + kEPS);
    }
}

// ---------------------------------------------------------------------------
// Kernel 4: finalize output (mode depends on out_size)
// ---------------------------------------------------------------------------
__global__ void finalize_kernel(float* __restrict__ out, int mode) {
    int t = blockIdx.x * blockDim.x + threadIdx.x;
    if (mode == 0) {  // [loss, assign...]
        if (t == 0) {
            float s = 0.0f;
            for (int b = 0; b < Bn; b++) s += g_loss[b];
            out[0] = s / (float)Bn;
        }
        if (t < Bn * Nn) out[1 + t] = (float)g_assign[t];
    } else if (mode == 1) {  // assign only
        if (t < Bn * Nn) out[t] = (float)g_assign[t];
    } else {  // loss only
        if (t == 0) {
            float s = 0.0f;
            for (int b = 0; b < Bn; b++) s += g_loss[b];
            out[0] = s / (float)Bn;
        }
    }
}

// ---------------------------------------------------------------------------
extern "C" void kernel_launch(void* const* d_in, const int* in_sizes, int n_in,
                              void* d_out, int out_size) {
    const float* pred_cat  = (const float*)d_in[0];
    const float* pred_bbox = (const float*)d_in[1];
    const int*   targ_cat  = (const int*)d_in[2];
    const float* targ_bbox = (const float*)d_in[3];
    float* out = (float*)d_out;

    int tot = Bn * Mn + Bn * Nn;
    prep_kernel<<<(tot + 127) / 128, 128>>>(pred_cat, pred_bbox, targ_bbox);

    dim3 gc(Nn, Bn);
    cost_kernel<<<gc, Mn>>>(pred_cat, targ_cat);

    cudaFuncSetAttribute(hungarian_kernel,
                         cudaFuncAttributeMaxDynamicSharedMemorySize, SMEM_TOTAL);
    hungarian_kernel<<<Bn, Mn, SMEM_TOTAL>>>(pred_cat, targ_cat);

    int mode;
    if (out_size == Bn * Nn + 1)      mode = 0;
    else if (out_size == Bn * Nn)     mode = 1;
    else                              mode = 2;
    finalize_kernel<<<(Bn * Nn + 127) / 128, 128>>>(out, mode);
}

// round 3
// speedup vs baseline: 2.0113x; 2.0113x over previous
#include <cuda_runtime.h>
#include <math.h>
#include <float.h>
#include <stdint.h>

// Problem constants
#define Bn 32
#define Mn 384
#define Nn 128
#define Cn 92

static __device__ __constant__ float kCOST_IOU = 2.0f;
static __device__ __constant__ float kCOST_L1  = 5.0f;
static __device__ __constant__ float kCOST_CAT = 1.0f;
static __device__ __constant__ float kEPS      = 1e-7f;

// Scratch (device globals: allocation-free)
__device__ float  g_cost[(size_t)Bn * Nn * Mn];   // [b][n][m]
__device__ float2 g_stats[Bn * Mn];               // (max, sumexp) per (b,m)
__device__ float4 g_pxy[Bn * Mn];                 // pred xyxy
__device__ float4 g_txy[Bn * Nn];                 // targ xyxy
__device__ int    g_assign[Bn * Nn];
__device__ float  g_loss[Bn];

// ---------------------------------------------------------------------------
// Kernel 1: per-(b,m) softmax stats + pred xyxy; per-(b,n) targ xyxy
// ---------------------------------------------------------------------------
__global__ void prep_kernel(const float* __restrict__ pred_cat,
                            const float* __restrict__ pred_bbox,
                            const float* __restrict__ targ_bbox) {
    int t = blockIdx.x * blockDim.x + threadIdx.x;
    if (t < Bn * Mn) {
        const float* row = pred_cat + (size_t)t * Cn;
        float mx = -FLT_MAX;
        for (int c = 0; c < Cn; c++) mx = fmaxf(mx, row[c]);
        float s = 0.0f;
        for (int c = 0; c < Cn; c++) s += expf(row[c] - mx);
        g_stats[t] = make_float2(mx, s);
        float cx = pred_bbox[t * 4 + 0], cy = pred_bbox[t * 4 + 1];
        float w  = pred_bbox[t * 4 + 2], h  = pred_bbox[t * 4 + 3];
        g_pxy[t] = make_float4(cx - 0.5f * w, cy - 0.5f * h,
                               cx + 0.5f * w, cy + 0.5f * h);
    } else if (t < Bn * Mn + Bn * Nn) {
        int u = t - Bn * Mn;
        float cx = targ_bbox[u * 4 + 0], cy = targ_bbox[u * 4 + 1];
        float w  = targ_bbox[u * 4 + 2], h  = targ_bbox[u * 4 + 3];
        g_txy[u] = make_float4(cx - 0.5f * w, cy - 0.5f * h,
                               cx + 0.5f * w, cy + 0.5f * h);
    }
}

// GIoU-loss + L1 helper (matches reference formula order)
__device__ __forceinline__ float bbox_pair_cost(float4 p, float4 t) {
    float ix1 = fmaxf(p.x, t.x), iy1 = fmaxf(p.y, t.y);
    float ix2 = fminf(p.z, t.z), iy2 = fminf(p.w, t.w);
    float inter = fmaxf(ix2 - ix1, 0.0f) * fmaxf(iy2 - iy1, 0.0f);
    float ap = (p.z - p.x) * (p.w - p.y);
    float at = (t.z - t.x) * (t.w - t.y);
    float un = ap + at - inter;
    float iou = inter / (un + kEPS);
    float cx1 = fminf(p.x, t.x), cy1 = fminf(p.y, t.y);
    float cx2 = fmaxf(p.z, t.z), cy2 = fmaxf(p.w, t.w);
    float ac = (cx2 - cx1) * (cy2 - cy1);
    float giou = iou - (ac - un) / (ac + kEPS);
    float gl = 1.0f - giou;
    float l1 = (fabsf(p.x - t.x) + fabsf(p.y - t.y) +
                fabsf(p.z - t.z) + fabsf(p.w - t.w)) * 0.25f;
    return kCOST_IOU * gl + kCOST_L1 * l1;
}

// ---------------------------------------------------------------------------
// Kernel 2: cost matrix, one block per (b,n), thread per m (coalesced writes)
// ---------------------------------------------------------------------------
__global__ __launch_bounds__(Mn) void cost_kernel(const float* __restrict__ pred_cat,
                                                  const int* __restrict__ targ_cat) {
    int b = blockIdx.y, n = blockIdx.x, m = threadIdx.x;
    int tc = targ_cat[b * Nn + n];
    float4 t4 = g_txy[b * Nn + n];
    float maskf = (tc != 0) ? 1.0f : 0.0f;

    float2 st = g_stats[b * Mn + m];
    float logit = pred_cat[((size_t)(b * Mn + m)) * Cn + tc];
    float prob = expf(logit - st.x) / st.y;
    float cat = kCOST_CAT * (1.0f - prob);

    float bb = bbox_pair_cost(g_pxy[b * Mn + m], t4);
    g_cost[((size_t)(b * Nn + n)) * Mn + m] = cat + bb * maskf;
}

// ---------------------------------------------------------------------------
// Kernel 3: Hungarian (JV) — block-per-batch, one thread per column.
// Register-resident per-column state (v, minv, used, cached p). 2 barriers
// per path step. f64 duals, exact numpy tie-break via sortable-u64 keys.
// ---------------------------------------------------------------------------
#define CS_BYTES   (Nn * Mn * 4)             // 196608
#define OFF_U      (CS_BYTES)                // double[Nn+1]
#define OFF_P      (OFF_U + (Nn + 1) * 8)    // int[Mn+1]
#define OFF_WAY    (OFF_P + (Mn + 1) * 4)    // int[Mn+1]
#define SMEM_TOTAL (OFF_WAY + (Mn + 1) * 4)  // ~200 KB dynamic

__device__ __forceinline__ unsigned fkey32(float f) {
    unsigned b = __float_as_uint(f);
    return (b & 0x80000000u) ? ~b : (b | 0x80000000u);
}
__device__ __forceinline__ unsigned long long dkey(double d) {
    unsigned long long b = (unsigned long long)__double_as_longlong(d);
    return (b & 0x8000000000000000ull) ? ~b : (b | 0x8000000000000000ull);
}
__device__ __forceinline__ double dunkey(unsigned long long k) {
    unsigned long long b = (k & 0x8000000000000000ull)
                         ? (k & 0x7FFFFFFFFFFFFFFFull) : ~k;
    return __longlong_as_double((long long)b);
}

__global__ __launch_bounds__(Mn, 1) void hungarian_kernel(
        const float* __restrict__ pred_cat,
        const int* __restrict__ targ_cat) {
    const unsigned FULL = 0xffffffffu;
    int b = blockIdx.x;
    extern __shared__ unsigned char smem[];
    float*  cs   = (float*)smem;
    double* u_sh = (double*)(smem + OFF_U);
    int*    p_sh = (int*)(smem + OFF_P);
    int*    way  = (int*)(smem + OFF_WAY);

    __shared__ unsigned long long wkey[12];
    __shared__ int   widx[12];
    __shared__ int   a_sh[Nn];
    __shared__ float r1[4], r2[4], r3[4];

    int tid = threadIdx.x;
    int wid = tid >> 5, lane = tid & 31;
    const int mycol = tid + 1;
    const double DINF = (double)INFINITY;

    // ---- stage cost tile into smem (float4) ----
    {
        const float4* gc = (const float4*)(g_cost + (size_t)b * Nn * Mn);
        float4* c4 = (float4*)cs;
        #pragma unroll 4
        for (int idx = tid; idx < Nn * Mn / 4; idx += Mn) c4[idx] = gc[idx];
    }
    p_sh[mycol] = 0;
    if (tid <= Nn) u_sh[tid] = 0.0;
    __syncthreads();

    double v_reg = 0.0;
    double minv;
    bool   used;
    int    my_p = 0;   // p[mycol] cached at the moment mycol joins the path

    for (int i = 1; i <= Nn; i++) {
        minv = DINF;
        used = false;
        int j0 = 0, i0 = i;   // path starts at virtual column 0, row i

        while (true) {
            // column j0 becomes used this iteration (virtual col 0: no owner)
            if (mycol == j0) used = true;

            double ui0 = u_sh[i0];                 // LDS broadcast

            unsigned long long key;
            float f32m;
            if (!used) {
                double cur = ((double)cs[(i0 - 1) * Mn + tid] - ui0) - v_reg;
                if (cur < minv) { minv = cur; way[mycol] = j0; }
                key  = dkey(minv);
                f32m = (float)minv;
            } else {
                key  = 0xFFFFFFFFFFFFFFFFull;
                f32m = FLT_MAX;                    // fkey(FLT_MAX) below INF's,
            }                                       // but key=MAX guards exactness
            int idx = mycol;

            // warp stage: f32 REDUX fast path, exact (u64,idx) chain on ties
            {
                unsigned fk = used ? 0xFFFFFFFFu : fkey32(f32m);
                unsigned rmin = __reduce_min_sync(FULL, fk);
                unsigned bal  = __ballot_sync(FULL, fk == rmin);
                if (__popc(bal) == 1) {
                    int w = __ffs(bal) - 1;
                    key = __shfl_sync(FULL, key, w);
                    idx = __shfl_sync(FULL, idx, w);
                } else {
                    #pragma unroll
                    for (int off = 16; off; off >>= 1) {
                        unsigned long long ok = __shfl_down_sync(FULL, key, off);
                        int                oi = __shfl_down_sync(FULL, idx, off);
                        if (ok < key || (ok == key && oi < idx)) { key = ok; idx = oi; }
                    }
                    key = __shfl_sync(FULL, key, 0);
                    idx = __shfl_sync(FULL, idx, 0);
                }
            }
            if (lane == 0) { wkey[wid] = key; widx[wid] = idx; }
            __syncthreads();                                        // (1)

            // block stage: every thread scans 12 pairs identically
            unsigned long long bk = wkey[0]; int bi = widx[0];
            #pragma unroll
            for (int w = 1; w < 12; w++) {
                unsigned long long k2 = wkey[w]; int i2 = widx[w];
                if (k2 < bk || (k2 == bk && i2 < bi)) { bk = k2; bi = i2; }
            }
            double delta = dunkey(bk);             // exact f64 minv[k]
            int k = bi;

            // dual updates (numpy f64 op order)
            if (used) {
                v_reg -= delta;
                u_sh[my_p] += delta;               // distinct rows, no race
            } else {
                minv -= delta;
            }
            if (tid == 0) u_sh[i] += delta;        // virtual column 0 (p[0]=i)

            int k_p = p_sh[k];                     // LDS broadcast
            if (mycol == k) my_p = k_p;            // cache before it's used
            j0 = k; i0 = k_p;
            __syncthreads();                                        // (2)
            if (k_p == 0) break;
        }

        // augment along alternating path (thread 0)
        if (tid == 0) {
            int jj = j0;
            while (jj) {
                int j1 = way[jj];
                p_sh[jj] = (j1 == 0) ? i : p_sh[j1];
                jj = j1;
            }
        }
        __syncthreads();
    }

    // ---- write assignment + inverse map ----
    {
        int pi = p_sh[mycol];
        if (pi > 0) {
            g_assign[b * Nn + (pi - 1)] = mycol - 1;
            a_sh[pi - 1] = mycol - 1;
        }
    }
    __syncthreads();

    // ---- fused per-batch loss ----
    float s_ce = 0.0f, s_bl = 0.0f, s_mk = 0.0f;
    if (tid < Nn) {
        int n  = tid;
        int a  = a_sh[n];
        int tc = targ_cat[b * Nn + n];
        float2 st = g_stats[b * Mn + a];
        float logit = pred_cat[((size_t)(b * Mn + a)) * Cn + tc];
        s_ce = -(logit - st.x - logf(st.y));
        float bl = bbox_pair_cost(g_pxy[b * Mn + a], g_txy[b * Nn + n]);
        s_mk = (tc != 0) ? 1.0f : 0.0f;
        s_bl = bl * s_mk;
    }
    #pragma unroll
    for (int off = 16; off; off >>= 1) {
        s_ce += __shfl_down_sync(FULL, s_ce, off);
        s_bl += __shfl_down_sync(FULL, s_bl, off);
        s_mk += __shfl_down_sync(FULL, s_mk, off);
    }
    if (wid < 4 && lane == 0) { r1[wid] = s_ce; r2[wid] = s_bl; r3[wid] = s_mk; }
    __syncthreads();
    if (tid == 0) {
        float ce_sum = r1[0] + r1[1] + r1[2] + r1[3];
        float bl_sum = r2[0] + r2[1] + r2[2] + r2[3];
        float mk_sum = r3[0] + r3[1] + r3[2] + r3[3];
        g_loss[b] = (ce_sum / (float)Nn) + bl_sum / (mk_sum + kEPS);
    }
}

// ---------------------------------------------------------------------------
// Kernel 4: finalize output (mode depends on out_size)
// ---------------------------------------------------------------------------
__global__ void finalize_kernel(float* __restrict__ out, int mode) {
    int t = blockIdx.x * blockDim.x + threadIdx.x;
    if (mode == 0) {  // [loss, assign...]
        if (t == 0) {
            float s = 0.0f;
            for (int b = 0; b < Bn; b++) s += g_loss[b];
            out[0] = s / (float)Bn;
        }
        if (t < Bn * Nn) out[1 + t] = (float)g_assign[t];
    } else if (mode == 1) {  // assign only
        if (t < Bn * Nn) out[t] = (float)g_assign[t];
    } else {  // loss only
        if (t == 0) {
            float s = 0.0f;
            for (int b = 0; b < Bn; b++) s += g_loss[b];
            out[0] = s / (float)Bn;
        }
    }
}

// ---------------------------------------------------------------------------
extern "C" void kernel_launch(void* const* d_in, const int* in_sizes, int n_in,
                              void* d_out, int out_size) {
    const float* pred_cat  = (const float*)d_in[0];
    const float* pred_bbox = (const float*)d_in[1];
    const int*   targ_cat  = (const int*)d_in[2];
    const float* targ_bbox = (const float*)d_in[3];
    float* out = (float*)d_out;

    int tot = Bn * Mn + Bn * Nn;
    prep_kernel<<<(tot + 127) / 128, 128>>>(pred_cat, pred_bbox, targ_bbox);

    dim3 gc(Nn, Bn);
    cost_kernel<<<gc, Mn>>>(pred_cat, targ_cat);

    cudaFuncSetAttribute(hungarian_kernel,
                         cudaFuncAttributeMaxDynamicSharedMemorySize, SMEM_TOTAL);
    hungarian_kernel<<<Bn, Mn, SMEM_TOTAL>>>(pred_cat, targ_cat);

    int mode;
    if (out_size == Bn * Nn + 1)      mode = 0;
    else if (out_size == Bn * Nn)     mode = 1;
    else                              mode = 2;
    finalize_kernel<<<(Bn * Nn + 127) / 128, 128>>>(out, mode);
}